// round 1
// baseline (speedup 1.0000x reference)
#include <cuda_runtime.h>

// Problem constants
#define B_SZ    2
#define S_LEN   2048
#define D_MODEL 1024
#define NHEAD   16
#define HD      64
#define M_ROWS  (B_SZ * S_LEN)      // 4096
#define QKV_LD  (3 * D_MODEL)       // 3072

// Scratch (device globals; no runtime allocation allowed)
__device__ float g_qkv [(size_t)M_ROWS * QKV_LD];   // [4096, 3072] : Q | K | V
__device__ float g_attn[(size_t)M_ROWS * D_MODEL];  // [4096, 1024] : attn out (B,S,H*HD)

// ---------------------------------------------------------------------------
// SGEMM: C[m,n] = sum_k A[m,k] * W[n,k] (+ bias[n])
// A: [M,K] row-major, W: [N,K] row-major (torch Linear weight), C: ldc stride.
// 128x128x8 tile, 256 threads, 8x8 microtile with split 4+64 layout
// (conflict-free float4 shared loads).
// All dims assumed multiples of tile sizes (true here: 4096/1024/3072/1024).
// ---------------------------------------------------------------------------
template <bool HAS_BIAS>
__global__ void __launch_bounds__(256) sgemm_xwT(
    const float* __restrict__ A, const float* __restrict__ W,
    const float* __restrict__ bias, float* __restrict__ C,
    int K, int ldc)
{
    __shared__ float As[8][128];
    __shared__ float Bs[8][128];

    const int tid = threadIdx.x;
    const int bm  = blockIdx.y * 128;
    const int bn  = blockIdx.x * 128;
    const int tr  = tid >> 4;   // 0..15
    const int tc  = tid & 15;   // 0..15

    float acc[8][8];
#pragma unroll
    for (int i = 0; i < 8; i++)
#pragma unroll
        for (int j = 0; j < 8; j++) acc[i][j] = 0.f;

    const int lm = tid >> 1;          // 0..127 : row within tile
    const int lk = (tid & 1) * 4;     // 0 or 4 : k offset
    const float* Ap = A + (size_t)(bm + lm) * K + lk;
    const float* Wp = W + (size_t)(bn + lm) * K + lk;

    for (int k0 = 0; k0 < K; k0 += 8) {
        float4 a4 = *reinterpret_cast<const float4*>(Ap + k0);
        float4 b4 = *reinterpret_cast<const float4*>(Wp + k0);
        As[lk + 0][lm] = a4.x; As[lk + 1][lm] = a4.y;
        As[lk + 2][lm] = a4.z; As[lk + 3][lm] = a4.w;
        Bs[lk + 0][lm] = b4.x; Bs[lk + 1][lm] = b4.y;
        Bs[lk + 2][lm] = b4.z; Bs[lk + 3][lm] = b4.w;
        __syncthreads();

#pragma unroll
        for (int kk = 0; kk < 8; kk++) {
            float4 a0 = *reinterpret_cast<const float4*>(&As[kk][tr * 4]);
            float4 a1 = *reinterpret_cast<const float4*>(&As[kk][tr * 4 + 64]);
            float4 b0 = *reinterpret_cast<const float4*>(&Bs[kk][tc * 4]);
            float4 b1 = *reinterpret_cast<const float4*>(&Bs[kk][tc * 4 + 64]);
            float av[8] = {a0.x, a0.y, a0.z, a0.w, a1.x, a1.y, a1.z, a1.w};
            float bv[8] = {b0.x, b0.y, b0.z, b0.w, b1.x, b1.y, b1.z, b1.w};
#pragma unroll
            for (int i = 0; i < 8; i++)
#pragma unroll
                for (int j = 0; j < 8; j++)
                    acc[i][j] += av[i] * bv[j];
        }
        __syncthreads();
    }

    // Epilogue: four 4x4 blocks per dim-half, float4 stores
#pragma unroll
    for (int ih = 0; ih < 2; ih++) {
#pragma unroll
        for (int ii = 0; ii < 4; ii++) {
            const int m = bm + ih * 64 + tr * 4 + ii;
#pragma unroll
            for (int jh = 0; jh < 2; jh++) {
                const int n = bn + jh * 64 + tc * 4;
                float4 v;
                v.x = acc[ih * 4 + ii][jh * 4 + 0];
                v.y = acc[ih * 4 + ii][jh * 4 + 1];
                v.z = acc[ih * 4 + ii][jh * 4 + 2];
                v.w = acc[ih * 4 + ii][jh * 4 + 3];
                if (HAS_BIAS) {
                    v.x += bias[n + 0]; v.y += bias[n + 1];
                    v.z += bias[n + 2]; v.w += bias[n + 3];
                }
                *reinterpret_cast<float4*>(&C[(size_t)m * ldc + n]) = v;
            }
        }
    }
}

// ---------------------------------------------------------------------------
// Causal flash attention forward.
// One CTA per (q-tile of 64, head, batch). 256 threads = 16(ty: q rows) x
// 16(tx: k cols / d cols). Q pre-scaled by 1/sqrt(HD). Online softmax with
// 16-lane shuffle reductions; P staged via smem for the PV product.
// Output written to g_attn in [B, S, H*HD] layout.
// ---------------------------------------------------------------------------
__global__ void __launch_bounds__(256) flash_fwd(
    const float* __restrict__ qkv, float* __restrict__ attn)
{
    extern __shared__ float sm[];
    float (*Qs)[65] = reinterpret_cast<float(*)[65]>(sm);
    float (*Ks)[65] = reinterpret_cast<float(*)[65]>(sm + 64 * 65);
    float (*Vs)[65] = reinterpret_cast<float(*)[65]>(sm + 2 * 64 * 65);
    float (*Ps)[65] = reinterpret_cast<float(*)[65]>(sm + 3 * 64 * 65);

    const int qt = blockIdx.x;   // 0..31
    const int h  = blockIdx.y;   // 0..15
    const int b  = blockIdx.z;   // 0..1
    const int tid = threadIdx.x;
    const int ty = tid >> 4;     // q-row group (4 rows)
    const int tx = tid & 15;     // k-col / d-col group (4 cols)
    const int q0 = ty * 4;
    const int d0 = tx * 4;

    const size_t head_base = (size_t)b * S_LEN * QKV_LD + (size_t)h * HD;

    // Load Q tile, pre-scaled by 1/sqrt(64)
    for (int i = tid; i < 64 * 64; i += 256) {
        const int r = i >> 6, c = i & 63;
        Qs[r][c] = qkv[head_base + (size_t)(qt * 64 + r) * QKV_LD + c] * 0.125f;
    }

    float o[4][4];
    float mi[4], li[4];
#pragma unroll
    for (int i = 0; i < 4; i++) {
        mi[i] = -1e30f; li[i] = 0.f;
#pragma unroll
        for (int j = 0; j < 4; j++) o[i][j] = 0.f;
    }

    for (int kt = 0; kt <= qt; kt++) {
        // Load K and V tiles
        for (int i = tid; i < 64 * 64; i += 256) {
            const int r = i >> 6, c = i & 63;
            const size_t g = head_base + (size_t)(kt * 64 + r) * QKV_LD + c;
            Ks[r][c] = qkv[g + D_MODEL];
            Vs[r][c] = qkv[g + 2 * D_MODEL];
        }
        __syncthreads();

        // S = Q @ K^T  (4x4 per thread)
        float s[4][4];
#pragma unroll
        for (int i = 0; i < 4; i++)
#pragma unroll
            for (int j = 0; j < 4; j++) s[i][j] = 0.f;

#pragma unroll 8
        for (int d = 0; d < 64; d++) {
            float aq[4], bk[4];
#pragma unroll
            for (int i = 0; i < 4; i++) aq[i] = Qs[q0 + i][d];
#pragma unroll
            for (int j = 0; j < 4; j++) bk[j] = Ks[tx * 4 + j][d];
#pragma unroll
            for (int i = 0; i < 4; i++)
#pragma unroll
                for (int j = 0; j < 4; j++)
                    s[i][j] += aq[i] * bk[j];
        }

        // Causal mask (diagonal tile only)
        if (kt == qt) {
#pragma unroll
            for (int i = 0; i < 4; i++)
#pragma unroll
                for (int j = 0; j < 4; j++)
                    if (tx * 4 + j > q0 + i) s[i][j] = -1e30f;
        }

        // Online softmax, reduced over the 16-lane tx group
        float p[4][4];
#pragma unroll
        for (int i = 0; i < 4; i++) {
            float rm = fmaxf(fmaxf(s[i][0], s[i][1]), fmaxf(s[i][2], s[i][3]));
#pragma unroll
            for (int off = 8; off >= 1; off >>= 1)
                rm = fmaxf(rm, __shfl_xor_sync(0xffffffffu, rm, off));

            const float nm    = fmaxf(mi[i], rm);
            const float alpha = __expf(mi[i] - nm);
            mi[i] = nm;

            float sum = 0.f;
#pragma unroll
            for (int j = 0; j < 4; j++) {
                p[i][j] = __expf(s[i][j] - nm);
                sum += p[i][j];
            }
#pragma unroll
            for (int off = 8; off >= 1; off >>= 1)
                sum += __shfl_xor_sync(0xffffffffu, sum, off);

            li[i] = li[i] * alpha + sum;
#pragma unroll
            for (int j = 0; j < 4; j++) o[i][j] *= alpha;
        }

        // Stage P
#pragma unroll
        for (int i = 0; i < 4; i++)
#pragma unroll
            for (int j = 0; j < 4; j++)
                Ps[q0 + i][tx * 4 + j] = p[i][j];
        __syncthreads();

        // O += P @ V
#pragma unroll 8
        for (int kk = 0; kk < 64; kk++) {
            float pp[4], vv[4];
#pragma unroll
            for (int i = 0; i < 4; i++) pp[i] = Ps[q0 + i][kk];
#pragma unroll
            for (int j = 0; j < 4; j++) vv[j] = Vs[kk][d0 + j];
#pragma unroll
            for (int i = 0; i < 4; i++)
#pragma unroll
                for (int j = 0; j < 4; j++)
                    o[i][j] += pp[i] * vv[j];
        }
        __syncthreads();
    }

    // Normalize and write to [B, S, H*HD]
    const size_t ob = ((size_t)b * S_LEN + qt * 64) * D_MODEL + (size_t)h * HD;
#pragma unroll
    for (int i = 0; i < 4; i++) {
        const float inv = 1.f / li[i];
        float4 v;
        v.x = o[i][0] * inv; v.y = o[i][1] * inv;
        v.z = o[i][2] * inv; v.w = o[i][3] * inv;
        *reinterpret_cast<float4*>(&attn[ob + (size_t)(q0 + i) * D_MODEL + d0]) = v;
    }
}

// ---------------------------------------------------------------------------
extern "C" void kernel_launch(void* const* d_in, const int* in_sizes, int n_in,
                              void* d_out, int out_size)
{
    const float* x    = (const float*)d_in[0];   // [2,2048,1024]
    const float* wq   = (const float*)d_in[1];   // [1024,1024]
    const float* wk   = (const float*)d_in[2];
    const float* wv   = (const float*)d_in[3];
    const float* wo_w = (const float*)d_in[4];
    const float* wo_b = (const float*)d_in[5];   // [1024]
    float* out = (float*)d_out;

    float* qkv;  cudaGetSymbolAddress((void**)&qkv,  g_qkv);
    float* attn; cudaGetSymbolAddress((void**)&attn, g_attn);

    static bool attr_done = false;
    const int flash_smem = 4 * 64 * 65 * (int)sizeof(float);  // 66560 B
    if (!attr_done) {
        cudaFuncSetAttribute(flash_fwd,
                             cudaFuncAttributeMaxDynamicSharedMemorySize,
                             flash_smem);
        attr_done = true;
    }

    const dim3 gemm_blk(256);
    const dim3 gemm_qkv_grid(D_MODEL / 128, M_ROWS / 128);  // (8, 32)

    // Q, K, V projections into g_qkv columns [0:1024), [1024:2048), [2048:3072)
    sgemm_xwT<false><<<gemm_qkv_grid, gemm_blk>>>(x, wq, nullptr, qkv + 0,            D_MODEL, QKV_LD);
    sgemm_xwT<false><<<gemm_qkv_grid, gemm_blk>>>(x, wk, nullptr, qkv + D_MODEL,      D_MODEL, QKV_LD);
    sgemm_xwT<false><<<gemm_qkv_grid, gemm_blk>>>(x, wv, nullptr, qkv + 2 * D_MODEL,  D_MODEL, QKV_LD);

    // Causal flash attention -> g_attn [B, S, H*HD]
    const dim3 flash_grid(S_LEN / 64, NHEAD, B_SZ);  // (32, 16, 2)
    flash_fwd<<<flash_grid, 256, flash_smem>>>(qkv, attn);

    // Output projection with bias -> d_out
    const dim3 gemm_o_grid(D_MODEL / 128, M_ROWS / 128);    // (8, 32)
    sgemm_xwT<true><<<gemm_o_grid, gemm_blk>>>(attn, wo_w, wo_b, out, D_MODEL, D_MODEL);
}

// round 2
// speedup vs baseline: 1.1590x; 1.1590x over previous
#include <cuda_runtime.h>

// Problem constants
#define B_SZ    2
#define S_LEN   2048
#define D_MODEL 1024
#define NHEAD   16
#define HD      64
#define M_ROWS  (B_SZ * S_LEN)      // 4096
#define QKV_LD  (3 * D_MODEL)       // 3072

// Scratch (device globals; no runtime allocation allowed)
__device__ float g_qkv [(size_t)M_ROWS * QKV_LD];   // [4096, 3072] : Q | K | V
__device__ float g_attn[(size_t)M_ROWS * D_MODEL];  // [4096, 1024] : attn out (B,S,H*HD)

// ---------------------------------------------------------------------------
// SGEMM v2: C[m,n] = sum_k A[m,k] * W[n,k] (+ bias[n])
// 128x128 tile, BK=16, double-buffered smem (transposed, pad 132),
// 256 threads, 8x8 microtile (blocked 4+64 split), register prefetch.
// ---------------------------------------------------------------------------
template <bool HAS_BIAS>
__global__ void __launch_bounds__(256, 2) sgemm_xwT(
    const float* __restrict__ A, const float* __restrict__ W,
    const float* __restrict__ bias, float* __restrict__ C,
    int K, int ldc)
{
    __shared__ float As[2][16][132];
    __shared__ float Bs[2][16][132];

    const int tid = threadIdx.x;
    const int bm  = blockIdx.y * 128;
    const int bn  = blockIdx.x * 128;
    const int tr  = tid >> 4;   // 0..15
    const int tc  = tid & 15;   // 0..15

    // Loader mapping: each thread handles 2 float4 per matrix per slab.
    const int r0 = tid >> 2;          // 0..63
    const int c4 = (tid & 3) * 4;     // 0,4,8,12

    const float* Ap = A + (size_t)(bm + r0) * K + c4;
    const float* Wp = W + (size_t)(bn + r0) * K + c4;
    const size_t rowskip = (size_t)64 * K;

    float acc[8][8];
#pragma unroll
    for (int i = 0; i < 8; i++)
#pragma unroll
        for (int j = 0; j < 8; j++) acc[i][j] = 0.f;

    // Prologue: load slab 0 into buffer 0
    {
        float4 pa0 = *reinterpret_cast<const float4*>(Ap);
        float4 pa1 = *reinterpret_cast<const float4*>(Ap + rowskip);
        float4 pb0 = *reinterpret_cast<const float4*>(Wp);
        float4 pb1 = *reinterpret_cast<const float4*>(Wp + rowskip);
        As[0][c4 + 0][r0] = pa0.x; As[0][c4 + 1][r0] = pa0.y;
        As[0][c4 + 2][r0] = pa0.z; As[0][c4 + 3][r0] = pa0.w;
        As[0][c4 + 0][r0 + 64] = pa1.x; As[0][c4 + 1][r0 + 64] = pa1.y;
        As[0][c4 + 2][r0 + 64] = pa1.z; As[0][c4 + 3][r0 + 64] = pa1.w;
        Bs[0][c4 + 0][r0] = pb0.x; Bs[0][c4 + 1][r0] = pb0.y;
        Bs[0][c4 + 2][r0] = pb0.z; Bs[0][c4 + 3][r0] = pb0.w;
        Bs[0][c4 + 0][r0 + 64] = pb1.x; Bs[0][c4 + 1][r0 + 64] = pb1.y;
        Bs[0][c4 + 2][r0 + 64] = pb1.z; Bs[0][c4 + 3][r0 + 64] = pb1.w;
    }
    __syncthreads();

    int buf = 0;
    for (int k0 = 16; k0 <= K; k0 += 16) {
        const bool more = (k0 < K);
        float4 pa0, pa1, pb0, pb1;
        if (more) {
            pa0 = *reinterpret_cast<const float4*>(Ap + k0);
            pa1 = *reinterpret_cast<const float4*>(Ap + k0 + rowskip);
            pb0 = *reinterpret_cast<const float4*>(Wp + k0);
            pb1 = *reinterpret_cast<const float4*>(Wp + k0 + rowskip);
        }

#pragma unroll
        for (int kk = 0; kk < 16; kk++) {
            float4 a0 = *reinterpret_cast<const float4*>(&As[buf][kk][tr * 4]);
            float4 a1 = *reinterpret_cast<const float4*>(&As[buf][kk][tr * 4 + 64]);
            float4 b0 = *reinterpret_cast<const float4*>(&Bs[buf][kk][tc * 4]);
            float4 b1 = *reinterpret_cast<const float4*>(&Bs[buf][kk][tc * 4 + 64]);
            float av[8] = {a0.x, a0.y, a0.z, a0.w, a1.x, a1.y, a1.z, a1.w};
            float bv[8] = {b0.x, b0.y, b0.z, b0.w, b1.x, b1.y, b1.z, b1.w};
#pragma unroll
            for (int i = 0; i < 8; i++)
#pragma unroll
                for (int j = 0; j < 8; j++)
                    acc[i][j] += av[i] * bv[j];
        }

        if (more) {
            const int nb = buf ^ 1;
            As[nb][c4 + 0][r0] = pa0.x; As[nb][c4 + 1][r0] = pa0.y;
            As[nb][c4 + 2][r0] = pa0.z; As[nb][c4 + 3][r0] = pa0.w;
            As[nb][c4 + 0][r0 + 64] = pa1.x; As[nb][c4 + 1][r0 + 64] = pa1.y;
            As[nb][c4 + 2][r0 + 64] = pa1.z; As[nb][c4 + 3][r0 + 64] = pa1.w;
            Bs[nb][c4 + 0][r0] = pb0.x; Bs[nb][c4 + 1][r0] = pb0.y;
            Bs[nb][c4 + 2][r0] = pb0.z; Bs[nb][c4 + 3][r0] = pb0.w;
            Bs[nb][c4 + 0][r0 + 64] = pb1.x; Bs[nb][c4 + 1][r0 + 64] = pb1.y;
            Bs[nb][c4 + 2][r0 + 64] = pb1.z; Bs[nb][c4 + 3][r0 + 64] = pb1.w;
        }
        __syncthreads();
        buf ^= 1;
    }

    // Epilogue: float4 stores, blocked 4+64 columns
#pragma unroll
    for (int ih = 0; ih < 2; ih++) {
#pragma unroll
        for (int ii = 0; ii < 4; ii++) {
            const int m = bm + ih * 64 + tr * 4 + ii;
#pragma unroll
            for (int jh = 0; jh < 2; jh++) {
                const int n = bn + jh * 64 + tc * 4;
                float4 v;
                v.x = acc[ih * 4 + ii][jh * 4 + 0];
                v.y = acc[ih * 4 + ii][jh * 4 + 1];
                v.z = acc[ih * 4 + ii][jh * 4 + 2];
                v.w = acc[ih * 4 + ii][jh * 4 + 3];
                if (HAS_BIAS) {
                    v.x += bias[n + 0]; v.y += bias[n + 1];
                    v.z += bias[n + 2]; v.w += bias[n + 3];
                }
                *reinterpret_cast<float4*>(&C[(size_t)m * ldc + n]) = v;
            }
        }
    }
}

// ---------------------------------------------------------------------------
// Causal flash attention v2.
// One CTA per (q-tile of 64, head, batch). 256 threads = 16(ty) x 16(tx).
// Strided column ownership (c = tx + 16j) -> conflict-free scalar K/V reads.
// Q and P tiles padded to 68 -> float4 broadcast reads along k-dim.
// ---------------------------------------------------------------------------
#define QP_PAD 68
#define KV_PAD 65
#define SM_QS  0
#define SM_KS  (64 * QP_PAD)                 // 4352
#define SM_VS  (SM_KS + 64 * KV_PAD)         // 8512
#define SM_PS  (SM_VS + 64 * KV_PAD)         // 12672
#define FLASH_SMEM_FLOATS (SM_PS + 64 * QP_PAD)   // 17024 floats = 68096 B

__global__ void __launch_bounds__(256) flash_fwd(
    const float* __restrict__ qkv, float* __restrict__ attn)
{
    extern __shared__ float sm[];
    float* Qs = sm + SM_QS;   // [64][68]
    float* Ks = sm + SM_KS;   // [64][65]
    float* Vs = sm + SM_VS;   // [64][65]
    float* Ps = sm + SM_PS;   // [64][68]

    const int qt = (gridDim.x - 1) - blockIdx.x;  // longest tiles first
    const int h  = blockIdx.y;
    const int b  = blockIdx.z;
    const int tid = threadIdx.x;
    const int ty = tid >> 4;
    const int tx = tid & 15;
    const int q0 = ty * 4;

    const size_t head_base = (size_t)b * S_LEN * QKV_LD + (size_t)h * HD;

    // Load Q tile (float4, pre-scaled by 1/sqrt(64)), store float4 to pad-68
#pragma unroll
    for (int t = 0; t < 4; t++) {
        const int fid = tid + t * 256;
        const int r = fid >> 4, cc = (fid & 15) * 4;
        float4 v = *reinterpret_cast<const float4*>(
            &qkv[head_base + (size_t)(qt * 64 + r) * QKV_LD + cc]);
        v.x *= 0.125f; v.y *= 0.125f; v.z *= 0.125f; v.w *= 0.125f;
        *reinterpret_cast<float4*>(&Qs[r * QP_PAD + cc]) = v;
    }

    float o[4][4];
    float mi[4], li[4];
#pragma unroll
    for (int i = 0; i < 4; i++) {
        mi[i] = -1e30f; li[i] = 0.f;
#pragma unroll
        for (int j = 0; j < 4; j++) o[i][j] = 0.f;
    }

    for (int kt = 0; kt <= qt; kt++) {
        // Load K and V tiles (float4 global, scalar stores to pad-65)
#pragma unroll
        for (int t = 0; t < 4; t++) {
            const int fid = tid + t * 256;
            const int r = fid >> 4, cc = (fid & 15) * 4;
            const size_t g = head_base + (size_t)(kt * 64 + r) * QKV_LD + cc;
            float4 kv = *reinterpret_cast<const float4*>(&qkv[g + D_MODEL]);
            float4 vv = *reinterpret_cast<const float4*>(&qkv[g + 2 * D_MODEL]);
            Ks[r * KV_PAD + cc + 0] = kv.x; Ks[r * KV_PAD + cc + 1] = kv.y;
            Ks[r * KV_PAD + cc + 2] = kv.z; Ks[r * KV_PAD + cc + 3] = kv.w;
            Vs[r * KV_PAD + cc + 0] = vv.x; Vs[r * KV_PAD + cc + 1] = vv.y;
            Vs[r * KV_PAD + cc + 2] = vv.z; Vs[r * KV_PAD + cc + 3] = vv.w;
        }
        __syncthreads();

        // S = Q @ K^T  (rows q0..q0+3, cols tx+16j)
        float s[4][4];
#pragma unroll
        for (int i = 0; i < 4; i++)
#pragma unroll
            for (int j = 0; j < 4; j++) s[i][j] = 0.f;

#pragma unroll 4
        for (int d4 = 0; d4 < 16; d4++) {
            float aq[4][4];
#pragma unroll
            for (int i = 0; i < 4; i++) {
                float4 v = *reinterpret_cast<const float4*>(
                    &Qs[(q0 + i) * QP_PAD + d4 * 4]);
                aq[i][0] = v.x; aq[i][1] = v.y; aq[i][2] = v.z; aq[i][3] = v.w;
            }
#pragma unroll
            for (int dd = 0; dd < 4; dd++) {
                float bk[4];
#pragma unroll
                for (int j = 0; j < 4; j++)
                    bk[j] = Ks[(tx + 16 * j) * KV_PAD + d4 * 4 + dd];
#pragma unroll
                for (int i = 0; i < 4; i++)
#pragma unroll
                    for (int j = 0; j < 4; j++)
                        s[i][j] += aq[i][dd] * bk[j];
            }
        }

        // Causal mask (diagonal tile only)
        if (kt == qt) {
#pragma unroll
            for (int i = 0; i < 4; i++)
#pragma unroll
                for (int j = 0; j < 4; j++)
                    if (tx + 16 * j > q0 + i) s[i][j] = -1e30f;
        }

        // Online softmax, reduced over the 16-lane tx group (s reused as P)
#pragma unroll
        for (int i = 0; i < 4; i++) {
            float rm = fmaxf(fmaxf(s[i][0], s[i][1]), fmaxf(s[i][2], s[i][3]));
#pragma unroll
            for (int off = 8; off >= 1; off >>= 1)
                rm = fmaxf(rm, __shfl_xor_sync(0xffffffffu, rm, off));

            const float nm    = fmaxf(mi[i], rm);
            const float alpha = __expf(mi[i] - nm);
            mi[i] = nm;

            float sum = 0.f;
#pragma unroll
            for (int j = 0; j < 4; j++) {
                s[i][j] = __expf(s[i][j] - nm);
                sum += s[i][j];
            }
#pragma unroll
            for (int off = 8; off >= 1; off >>= 1)
                sum += __shfl_xor_sync(0xffffffffu, sum, off);

            li[i] = li[i] * alpha + sum;
#pragma unroll
            for (int j = 0; j < 4; j++) o[i][j] *= alpha;
        }

        // Stage P (conflict-free: consecutive tx -> consecutive banks)
#pragma unroll
        for (int i = 0; i < 4; i++)
#pragma unroll
            for (int j = 0; j < 4; j++)
                Ps[(q0 + i) * QP_PAD + tx + 16 * j] = s[i][j];
        __syncthreads();

        // O += P @ V  (P float4 broadcast, V scalar conflict-free)
#pragma unroll 4
        for (int k4 = 0; k4 < 16; k4++) {
            float pp[4][4];
#pragma unroll
            for (int i = 0; i < 4; i++) {
                float4 v = *reinterpret_cast<const float4*>(
                    &Ps[(q0 + i) * QP_PAD + k4 * 4]);
                pp[i][0] = v.x; pp[i][1] = v.y; pp[i][2] = v.z; pp[i][3] = v.w;
            }
#pragma unroll
            for (int dd = 0; dd < 4; dd++) {
                float vv[4];
#pragma unroll
                for (int j = 0; j < 4; j++)
                    vv[j] = Vs[(k4 * 4 + dd) * KV_PAD + tx + 16 * j];
#pragma unroll
                for (int i = 0; i < 4; i++)
#pragma unroll
                    for (int j = 0; j < 4; j++)
                        o[i][j] += pp[i][dd] * vv[j];
            }
        }
        __syncthreads();
    }

    // Normalize and write to [B, S, H*HD] (scalar, coalesced per j)
    const size_t ob = ((size_t)b * S_LEN + qt * 64) * D_MODEL + (size_t)h * HD;
#pragma unroll
    for (int i = 0; i < 4; i++) {
        const float inv = 1.f / li[i];
#pragma unroll
        for (int j = 0; j < 4; j++)
            attn[ob + (size_t)(q0 + i) * D_MODEL + tx + 16 * j] = o[i][j] * inv;
    }
}

// ---------------------------------------------------------------------------
extern "C" void kernel_launch(void* const* d_in, const int* in_sizes, int n_in,
                              void* d_out, int out_size)
{
    const float* x    = (const float*)d_in[0];   // [2,2048,1024]
    const float* wq   = (const float*)d_in[1];   // [1024,1024]
    const float* wk   = (const float*)d_in[2];
    const float* wv   = (const float*)d_in[3];
    const float* wo_w = (const float*)d_in[4];
    const float* wo_b = (const float*)d_in[5];   // [1024]
    float* out = (float*)d_out;

    float* qkv;  cudaGetSymbolAddress((void**)&qkv,  g_qkv);
    float* attn; cudaGetSymbolAddress((void**)&attn, g_attn);

    static bool attr_done = false;
    const int flash_smem = FLASH_SMEM_FLOATS * (int)sizeof(float);  // 68096 B
    if (!attr_done) {
        cudaFuncSetAttribute(flash_fwd,
                             cudaFuncAttributeMaxDynamicSharedMemorySize,
                             flash_smem);
        attr_done = true;
    }

    const dim3 gemm_blk(256);
    const dim3 gemm_grid(D_MODEL / 128, M_ROWS / 128);  // (8, 32)

    // Q, K, V projections into g_qkv columns [0:1024), [1024:2048), [2048:3072)
    sgemm_xwT<false><<<gemm_grid, gemm_blk>>>(x, wq, nullptr, qkv + 0,           D_MODEL, QKV_LD);
    sgemm_xwT<false><<<gemm_grid, gemm_blk>>>(x, wk, nullptr, qkv + D_MODEL,     D_MODEL, QKV_LD);
    sgemm_xwT<false><<<gemm_grid, gemm_blk>>>(x, wv, nullptr, qkv + 2 * D_MODEL, D_MODEL, QKV_LD);

    // Causal flash attention -> g_attn [B, S, H*HD]
    const dim3 flash_grid(S_LEN / 64, NHEAD, B_SZ);  // (32, 16, 2)
    flash_fwd<<<flash_grid, 256, flash_smem>>>(qkv, attn);

    // Output projection with bias -> d_out
    sgemm_xwT<true><<<gemm_grid, gemm_blk>>>(attn, wo_w, wo_b, out, D_MODEL, D_MODEL);
}

// round 3
// speedup vs baseline: 1.1683x; 1.0081x over previous
#include <cuda_runtime.h>

// Problem constants
#define B_SZ    2
#define S_LEN   2048
#define D_MODEL 1024
#define NHEAD   16
#define HD      64
#define M_ROWS  (B_SZ * S_LEN)      // 4096
#define QKV_LD  (3 * D_MODEL)       // 3072

// Scratch (device globals; no runtime allocation allowed)
__device__ float g_qkv [(size_t)M_ROWS * QKV_LD];   // [4096, 3072] : Q | K | V
__device__ float g_attn[(size_t)M_ROWS * D_MODEL];  // [4096, 1024] : attn out (B,S,H*HD)

// ---------------------------------------------------------------------------
// SGEMM (unchanged from R2 — matched prediction at ~49 TF/s):
// C[m,n] = sum_k A[m,k] * W[n,k] (+ bias[n])
// 128x128 tile, BK=16, double-buffered smem (transposed, pad 132),
// 256 threads, 8x8 microtile, register prefetch.
// ---------------------------------------------------------------------------
template <bool HAS_BIAS>
__global__ void __launch_bounds__(256, 2) sgemm_xwT(
    const float* __restrict__ A, const float* __restrict__ W,
    const float* __restrict__ bias, float* __restrict__ C,
    int K, int ldc)
{
    __shared__ float As[2][16][132];
    __shared__ float Bs[2][16][132];

    const int tid = threadIdx.x;
    const int bm  = blockIdx.y * 128;
    const int bn  = blockIdx.x * 128;
    const int tr  = tid >> 4;
    const int tc  = tid & 15;

    const int r0 = tid >> 2;
    const int c4 = (tid & 3) * 4;

    const float* Ap = A + (size_t)(bm + r0) * K + c4;
    const float* Wp = W + (size_t)(bn + r0) * K + c4;
    const size_t rowskip = (size_t)64 * K;

    float acc[8][8];
#pragma unroll
    for (int i = 0; i < 8; i++)
#pragma unroll
        for (int j = 0; j < 8; j++) acc[i][j] = 0.f;

    {
        float4 pa0 = *reinterpret_cast<const float4*>(Ap);
        float4 pa1 = *reinterpret_cast<const float4*>(Ap + rowskip);
        float4 pb0 = *reinterpret_cast<const float4*>(Wp);
        float4 pb1 = *reinterpret_cast<const float4*>(Wp + rowskip);
        As[0][c4 + 0][r0] = pa0.x; As[0][c4 + 1][r0] = pa0.y;
        As[0][c4 + 2][r0] = pa0.z; As[0][c4 + 3][r0] = pa0.w;
        As[0][c4 + 0][r0 + 64] = pa1.x; As[0][c4 + 1][r0 + 64] = pa1.y;
        As[0][c4 + 2][r0 + 64] = pa1.z; As[0][c4 + 3][r0 + 64] = pa1.w;
        Bs[0][c4 + 0][r0] = pb0.x; Bs[0][c4 + 1][r0] = pb0.y;
        Bs[0][c4 + 2][r0] = pb0.z; Bs[0][c4 + 3][r0] = pb0.w;
        Bs[0][c4 + 0][r0 + 64] = pb1.x; Bs[0][c4 + 1][r0 + 64] = pb1.y;
        Bs[0][c4 + 2][r0 + 64] = pb1.z; Bs[0][c4 + 3][r0 + 64] = pb1.w;
    }
    __syncthreads();

    int buf = 0;
    for (int k0 = 16; k0 <= K; k0 += 16) {
        const bool more = (k0 < K);
        float4 pa0, pa1, pb0, pb1;
        if (more) {
            pa0 = *reinterpret_cast<const float4*>(Ap + k0);
            pa1 = *reinterpret_cast<const float4*>(Ap + k0 + rowskip);
            pb0 = *reinterpret_cast<const float4*>(Wp + k0);
            pb1 = *reinterpret_cast<const float4*>(Wp + k0 + rowskip);
        }

#pragma unroll
        for (int kk = 0; kk < 16; kk++) {
            float4 a0 = *reinterpret_cast<const float4*>(&As[buf][kk][tr * 4]);
            float4 a1 = *reinterpret_cast<const float4*>(&As[buf][kk][tr * 4 + 64]);
            float4 b0 = *reinterpret_cast<const float4*>(&Bs[buf][kk][tc * 4]);
            float4 b1 = *reinterpret_cast<const float4*>(&Bs[buf][kk][tc * 4 + 64]);
            float av[8] = {a0.x, a0.y, a0.z, a0.w, a1.x, a1.y, a1.z, a1.w};
            float bv[8] = {b0.x, b0.y, b0.z, b0.w, b1.x, b1.y, b1.z, b1.w};
#pragma unroll
            for (int i = 0; i < 8; i++)
#pragma unroll
                for (int j = 0; j < 8; j++)
                    acc[i][j] += av[i] * bv[j];
        }

        if (more) {
            const int nb = buf ^ 1;
            As[nb][c4 + 0][r0] = pa0.x; As[nb][c4 + 1][r0] = pa0.y;
            As[nb][c4 + 2][r0] = pa0.z; As[nb][c4 + 3][r0] = pa0.w;
            As[nb][c4 + 0][r0 + 64] = pa1.x; As[nb][c4 + 1][r0 + 64] = pa1.y;
            As[nb][c4 + 2][r0 + 64] = pa1.z; As[nb][c4 + 3][r0 + 64] = pa1.w;
            Bs[nb][c4 + 0][r0] = pb0.x; Bs[nb][c4 + 1][r0] = pb0.y;
            Bs[nb][c4 + 2][r0] = pb0.z; Bs[nb][c4 + 3][r0] = pb0.w;
            Bs[nb][c4 + 0][r0 + 64] = pb1.x; Bs[nb][c4 + 1][r0 + 64] = pb1.y;
            Bs[nb][c4 + 2][r0 + 64] = pb1.z; Bs[nb][c4 + 3][r0 + 64] = pb1.w;
        }
        __syncthreads();
        buf ^= 1;
    }

#pragma unroll
    for (int ih = 0; ih < 2; ih++) {
#pragma unroll
        for (int ii = 0; ii < 4; ii++) {
            const int m = bm + ih * 64 + tr * 4 + ii;
#pragma unroll
            for (int jh = 0; jh < 2; jh++) {
                const int n = bn + jh * 64 + tc * 4;
                float4 v;
                v.x = acc[ih * 4 + ii][jh * 4 + 0];
                v.y = acc[ih * 4 + ii][jh * 4 + 1];
                v.z = acc[ih * 4 + ii][jh * 4 + 2];
                v.w = acc[ih * 4 + ii][jh * 4 + 3];
                if (HAS_BIAS) {
                    v.x += bias[n + 0]; v.y += bias[n + 1];
                    v.z += bias[n + 2]; v.w += bias[n + 3];
                }
                *reinterpret_cast<float4*>(&C[(size_t)m * ldc + n]) = v;
            }
        }
    }
}

// ---------------------------------------------------------------------------
// Causal flash attention v3: all-LDS.128 inner loops.
// 64x64 tiles, XOR-swizzled smem (16B granules, g ^= (row>>2)&7, no padding).
// K stored TRANSPOSED (Kt[d][kcol]) so both QK and PV contract with float4
// reads on both operands. Thread (ty,tx) owns q rows 4ty..+3 and contiguous
// cols 4tx..+3. 256 threads, 4 tiles x 16KB = 64KB smem.
// ---------------------------------------------------------------------------
#define SM_QS  0
#define SM_KT  4096
#define SM_VS  8192
#define SM_PS  12288
#define FLASH_SMEM_BYTES (4 * 4096 * 4)   // 65536

// word index of 16B-granule g in row `row` of a 64-wide swizzled tile
__device__ __forceinline__ int swz(int row, int g) {
    return row * 64 + (((g) ^ ((row >> 2) & 7)) << 2);
}

__global__ void __launch_bounds__(256) flash_fwd(
    const float* __restrict__ qkv, float* __restrict__ attn)
{
    extern __shared__ float sm[];
    float* Qs = sm + SM_QS;   // [64 q][64 d]   swizzled
    float* Kt = sm + SM_KT;   // [64 d][64 kcol] swizzled (transposed)
    float* Vs = sm + SM_VS;   // [64 kk][64 d]  swizzled
    float* Ps = sm + SM_PS;   // [64 q][64 kcol] swizzled

    const int qt = (gridDim.x - 1) - blockIdx.x;  // longest tiles first
    const int h  = blockIdx.y;
    const int b  = blockIdx.z;
    const int tid = threadIdx.x;
    const int ty = tid >> 4;
    const int tx = tid & 15;
    const int q0 = ty * 4;

    const size_t head_base = (size_t)b * S_LEN * QKV_LD + (size_t)h * HD;

    // Load Q tile (float4, pre-scaled by 1/8), swizzled store
#pragma unroll
    for (int t = 0; t < 4; t++) {
        const int fid = tid + t * 256;
        const int r = fid >> 4, gc = fid & 15;
        float4 v = *reinterpret_cast<const float4*>(
            &qkv[head_base + (size_t)(qt * 64 + r) * QKV_LD + gc * 4]);
        v.x *= 0.125f; v.y *= 0.125f; v.z *= 0.125f; v.w *= 0.125f;
        *reinterpret_cast<float4*>(&Qs[swz(r, gc)]) = v;
    }

    float o[4][4];
    float mi[4], li[4];
#pragma unroll
    for (int i = 0; i < 4; i++) {
        mi[i] = -1e30f; li[i] = 0.f;
#pragma unroll
        for (int j = 0; j < 4; j++) o[i][j] = 0.f;
    }

    for (int kt = 0; kt <= qt; kt++) {
        // Load K (transposed scalar store) and V (float4 swizzled store)
#pragma unroll
        for (int t = 0; t < 4; t++) {
            const int fid = tid + t * 256;
            const int r = fid >> 4, gc = fid & 15;
            const size_t g = head_base + (size_t)(kt * 64 + r) * QKV_LD + gc * 4;
            float4 kv = *reinterpret_cast<const float4*>(&qkv[g + D_MODEL]);
            float4 vv = *reinterpret_cast<const float4*>(&qkv[g + 2 * D_MODEL]);
            // K row r (kcol=r), d = 4*gc+k  -> Kt[d][r]
            const int gk = ((r >> 2) ^ (gc & 7)) << 2;   // granule<<2, (d>>2)&7 == gc&7
            const int w  = r & 3;
            Kt[(4 * gc + 0) * 64 + gk + w] = kv.x;
            Kt[(4 * gc + 1) * 64 + gk + w] = kv.y;
            Kt[(4 * gc + 2) * 64 + gk + w] = kv.z;
            Kt[(4 * gc + 3) * 64 + gk + w] = kv.w;
            *reinterpret_cast<float4*>(&Vs[swz(r, gc)]) = vv;
        }
        __syncthreads();

        // S = Q @ K^T  (rows q0..+3, cols 4tx..+3), all float4 LDS
        float s[4][4];
#pragma unroll
        for (int i = 0; i < 4; i++)
#pragma unroll
            for (int j = 0; j < 4; j++) s[i][j] = 0.f;

#pragma unroll 4
        for (int d4 = 0; d4 < 16; d4++) {
            float4 aq[4], bk[4];
#pragma unroll
            for (int i = 0; i < 4; i++)
                aq[i] = *reinterpret_cast<const float4*>(&Qs[swz(q0 + i, d4)]);
#pragma unroll
            for (int dd = 0; dd < 4; dd++)
                bk[dd] = *reinterpret_cast<const float4*>(
                    &Kt[(4 * d4 + dd) * 64 + ((tx ^ (d4 & 7)) << 2)]);
#pragma unroll
            for (int i = 0; i < 4; i++) {
                const float a0 = aq[i].x, a1 = aq[i].y, a2 = aq[i].z, a3 = aq[i].w;
                s[i][0] += a0 * bk[0].x; s[i][1] += a0 * bk[0].y;
                s[i][2] += a0 * bk[0].z; s[i][3] += a0 * bk[0].w;
                s[i][0] += a1 * bk[1].x; s[i][1] += a1 * bk[1].y;
                s[i][2] += a1 * bk[1].z; s[i][3] += a1 * bk[1].w;
                s[i][0] += a2 * bk[2].x; s[i][1] += a2 * bk[2].y;
                s[i][2] += a2 * bk[2].z; s[i][3] += a2 * bk[2].w;
                s[i][0] += a3 * bk[3].x; s[i][1] += a3 * bk[3].y;
                s[i][2] += a3 * bk[3].z; s[i][3] += a3 * bk[3].w;
            }
        }

        // Causal mask (diagonal tile only); owned cols are 4tx..+3
        if (kt == qt) {
#pragma unroll
            for (int i = 0; i < 4; i++)
#pragma unroll
                for (int j = 0; j < 4; j++)
                    if (4 * tx + j > q0 + i) s[i][j] = -1e30f;
        }

        // Online softmax over the 16-lane tx group (s reused as P)
#pragma unroll
        for (int i = 0; i < 4; i++) {
            float rm = fmaxf(fmaxf(s[i][0], s[i][1]), fmaxf(s[i][2], s[i][3]));
#pragma unroll
            for (int off = 8; off >= 1; off >>= 1)
                rm = fmaxf(rm, __shfl_xor_sync(0xffffffffu, rm, off));

            const float nm    = fmaxf(mi[i], rm);
            const float alpha = __expf(mi[i] - nm);
            mi[i] = nm;

            float sum = 0.f;
#pragma unroll
            for (int j = 0; j < 4; j++) {
                s[i][j] = __expf(s[i][j] - nm);
                sum += s[i][j];
            }
#pragma unroll
            for (int off = 8; off >= 1; off >>= 1)
                sum += __shfl_xor_sync(0xffffffffu, sum, off);

            li[i] = li[i] * alpha + sum;
#pragma unroll
            for (int j = 0; j < 4; j++) o[i][j] *= alpha;
        }

        // Stage P: float4 store, swizzled
#pragma unroll
        for (int i = 0; i < 4; i++) {
            float4 v; v.x = s[i][0]; v.y = s[i][1]; v.z = s[i][2]; v.w = s[i][3];
            *reinterpret_cast<float4*>(&Ps[swz(q0 + i, tx)]) = v;
        }
        __syncthreads();

        // O += P @ V : all float4 LDS
#pragma unroll 4
        for (int k4 = 0; k4 < 16; k4++) {
            float4 pp[4], vv[4];
#pragma unroll
            for (int i = 0; i < 4; i++)
                pp[i] = *reinterpret_cast<const float4*>(&Ps[swz(q0 + i, k4)]);
#pragma unroll
            for (int dd = 0; dd < 4; dd++)
                vv[dd] = *reinterpret_cast<const float4*>(
                    &Vs[(4 * k4 + dd) * 64 + ((tx ^ (k4 & 7)) << 2)]);
#pragma unroll
            for (int i = 0; i < 4; i++) {
                const float p0 = pp[i].x, p1 = pp[i].y, p2 = pp[i].z, p3 = pp[i].w;
                o[i][0] += p0 * vv[0].x; o[i][1] += p0 * vv[0].y;
                o[i][2] += p0 * vv[0].z; o[i][3] += p0 * vv[0].w;
                o[i][0] += p1 * vv[1].x; o[i][1] += p1 * vv[1].y;
                o[i][2] += p1 * vv[1].z; o[i][3] += p1 * vv[1].w;
                o[i][0] += p2 * vv[2].x; o[i][1] += p2 * vv[2].y;
                o[i][2] += p2 * vv[2].z; o[i][3] += p2 * vv[2].w;
                o[i][0] += p3 * vv[3].x; o[i][1] += p3 * vv[3].y;
                o[i][2] += p3 * vv[3].z; o[i][3] += p3 * vv[3].w;
            }
        }
        __syncthreads();
    }

    // Normalize and write to [B, S, H*HD] — float4 stores
    const size_t ob = ((size_t)b * S_LEN + qt * 64) * D_MODEL + (size_t)h * HD;
#pragma unroll
    for (int i = 0; i < 4; i++) {
        const float inv = 1.f / li[i];
        float4 v;
        v.x = o[i][0] * inv; v.y = o[i][1] * inv;
        v.z = o[i][2] * inv; v.w = o[i][3] * inv;
        *reinterpret_cast<float4*>(
            &attn[ob + (size_t)(q0 + i) * D_MODEL + 4 * tx]) = v;
    }
}

// ---------------------------------------------------------------------------
extern "C" void kernel_launch(void* const* d_in, const int* in_sizes, int n_in,
                              void* d_out, int out_size)
{
    const float* x    = (const float*)d_in[0];
    const float* wq   = (const float*)d_in[1];
    const float* wk   = (const float*)d_in[2];
    const float* wv   = (const float*)d_in[3];
    const float* wo_w = (const float*)d_in[4];
    const float* wo_b = (const float*)d_in[5];
    float* out = (float*)d_out;

    float* qkv;  cudaGetSymbolAddress((void**)&qkv,  g_qkv);
    float* attn; cudaGetSymbolAddress((void**)&attn, g_attn);

    static bool attr_done = false;
    if (!attr_done) {
        cudaFuncSetAttribute(flash_fwd,
                             cudaFuncAttributeMaxDynamicSharedMemorySize,
                             FLASH_SMEM_BYTES);
        attr_done = true;
    }

    const dim3 gemm_blk(256);
    const dim3 gemm_grid(D_MODEL / 128, M_ROWS / 128);  // (8, 32)

    sgemm_xwT<false><<<gemm_grid, gemm_blk>>>(x, wq, nullptr, qkv + 0,           D_MODEL, QKV_LD);
    sgemm_xwT<false><<<gemm_grid, gemm_blk>>>(x, wk, nullptr, qkv + D_MODEL,     D_MODEL, QKV_LD);
    sgemm_xwT<false><<<gemm_grid, gemm_blk>>>(x, wv, nullptr, qkv + 2 * D_MODEL, D_MODEL, QKV_LD);

    const dim3 flash_grid(S_LEN / 64, NHEAD, B_SZ);  // (32, 16, 2)
    flash_fwd<<<flash_grid, 256, FLASH_SMEM_BYTES>>>(qkv, attn);

    sgemm_xwT<true><<<gemm_grid, gemm_blk>>>(attn, wo_w, wo_b, out, D_MODEL, D_MODEL);
}